// round 2
// baseline (speedup 1.0000x reference)
#include <cuda_runtime.h>
#include <cstdint>

#define NUM_USERS 100000
#define NUM_ITEMS 200000
#define NUM_NODES (NUM_USERS + NUM_ITEMS)
#define DIM 64
#define NUM_EDGES 2000000
#define NFLOAT ((long)NUM_NODES * DIM)        // 19,200,000
#define N4 (NFLOAT / 4)                       // 4,800,000 float4s

// Scratch: three node-feature buffers (76.8 MB each) as device globals
// (allocation inside kernel_launch is forbidden; __device__ globals are the
// sanctioned workaround).
__device__ float g_bufA[NFLOAT];
__device__ float g_bufB[NFLOAT];
__device__ float g_acc [NFLOAT];

// ---------------------------------------------------------------------------
// Init: x = concat(user_emb, item_emb); acc = x; y (bufB) = 0
// ---------------------------------------------------------------------------
__global__ void k_init(const float4* __restrict__ user4,
                       const float4* __restrict__ item4) {
    long i = (long)blockIdx.x * blockDim.x + threadIdx.x;
    if (i >= N4) return;
    const long uf4 = (long)NUM_USERS * DIM / 4;
    float4 v = (i < uf4) ? user4[i] : item4[i - uf4];
    ((float4*)g_bufA)[i] = v;
    ((float4*)g_acc )[i] = v;
    ((float4*)g_bufB)[i] = make_float4(0.f, 0.f, 0.f, 0.f);
}

// ---------------------------------------------------------------------------
// Scatter: y[src[e]] += x[dst[e]] * val[e]   (16 lanes/edge, float4/lane,
// vectorized f32x4 reduction — no return value, 1 LTS op per 16 B)
// ---------------------------------------------------------------------------
__global__ void k_scatter(const float4* __restrict__ x4,
                          float4*       __restrict__ y4,
                          const int*    __restrict__ esrc,
                          const int*    __restrict__ edst,
                          const float*  __restrict__ eval) {
    long t = (long)blockIdx.x * blockDim.x + threadIdx.x;
    long e = t >> 4;          // edge index
    int  c = (int)(t & 15);   // float4 chunk within the 64-dim row
    if (e >= NUM_EDGES) return;

    int   s = esrc[e];
    int   d = edst[e];
    float v = eval[e];

    float4 m = __ldg(x4 + (long)d * 16 + c);
    m.x *= v; m.y *= v; m.z *= v; m.w *= v;

    float4* addr = y4 + (long)s * 16 + c;
    asm volatile("red.global.add.v4.f32 [%0], {%1, %2, %3, %4};"
                 :: "l"(addr), "f"(m.x), "f"(m.y), "f"(m.z), "f"(m.w)
                 : "memory");
}

// ---------------------------------------------------------------------------
// Accumulate layer output into acc, and zero the buffer that will receive the
// NEXT layer's scatter (fused to avoid an extra full-buffer pass).
// ---------------------------------------------------------------------------
__global__ void k_accum(const float4* __restrict__ y4,
                        float4*       __restrict__ acc4,
                        float4*       __restrict__ zero4) {
    long i = (long)blockIdx.x * blockDim.x + threadIdx.x;
    if (i >= N4) return;
    float4 a = acc4[i];
    float4 b = y4[i];
    a.x += b.x; a.y += b.y; a.z += b.z; a.w += b.w;
    acc4[i]  = a;
    zero4[i] = make_float4(0.f, 0.f, 0.f, 0.f);
}

// ---------------------------------------------------------------------------
// Final: out = (acc + y_last) / 4   (users rows then items rows == node order)
// ---------------------------------------------------------------------------
__global__ void k_final(const float4* __restrict__ y4,
                        const float4* __restrict__ acc4,
                        float4*       __restrict__ out4) {
    long i = (long)blockIdx.x * blockDim.x + threadIdx.x;
    if (i >= N4) return;
    float4 a = acc4[i];
    float4 b = y4[i];
    a.x = (a.x + b.x) * 0.25f;
    a.y = (a.y + b.y) * 0.25f;
    a.z = (a.z + b.z) * 0.25f;
    a.w = (a.w + b.w) * 0.25f;
    out4[i] = a;
}

extern "C" void kernel_launch(void* const* d_in, const int* in_sizes, int n_in,
                              void* d_out, int out_size) {
    const float4* user4 = (const float4*)d_in[0];
    const float4* item4 = (const float4*)d_in[1];
    const float*  eval  = (const float*) d_in[2];
    const int*    esrc  = (const int*)   d_in[3];
    const int*    edst  = (const int*)   d_in[4];
    float4*       out4  = (float4*)d_out;

    void *pA, *pB, *pAcc;
    cudaGetSymbolAddress(&pA,   g_bufA);
    cudaGetSymbolAddress(&pB,   g_bufB);
    cudaGetSymbolAddress(&pAcc, g_acc);
    float4* A   = (float4*)pA;
    float4* B   = (float4*)pB;
    float4* ACC = (float4*)pAcc;

    const int TB = 256;
    const long elem_blocks    = (N4 + TB - 1) / TB;                    // 18750
    const long scatter_blocks = ((long)NUM_EDGES * 16 + TB - 1) / TB;  // 125000

    // x0 in A, acc = x0, B zeroed
    k_init<<<(unsigned)elem_blocks, TB>>>(user4, item4);

    // Layer 1: A -> B ; acc += B ; zero A
    k_scatter<<<(unsigned)scatter_blocks, TB>>>(A, B, esrc, edst, eval);
    k_accum  <<<(unsigned)elem_blocks,   TB>>>(B, ACC, A);

    // Layer 2: B -> A ; acc += A ; zero B
    k_scatter<<<(unsigned)scatter_blocks, TB>>>(B, A, esrc, edst, eval);
    k_accum  <<<(unsigned)elem_blocks,   TB>>>(A, ACC, B);

    // Layer 3: A -> B ; out = (acc + B) / 4
    k_scatter<<<(unsigned)scatter_blocks, TB>>>(A, B, esrc, edst, eval);
    k_final  <<<(unsigned)elem_blocks,   TB>>>(B, ACC, out4);
}

// round 3
// speedup vs baseline: 1.2285x; 1.2285x over previous
#include <cuda_runtime.h>
#include <cstdint>

#define NUM_USERS 100000
#define NUM_ITEMS 200000
#define NUM_NODES (NUM_USERS + NUM_ITEMS)
#define DIM 64
#define NUM_EDGES 2000000
#define NFLOAT ((long)NUM_NODES * DIM)        // 19,200,000 floats
#define N4 (NFLOAT / 4)                       // 4,800,000 float4s

// Three layer-output buffers (76.8 MB each). __device__ globals: the
// sanctioned scratch mechanism (no allocation allowed in kernel_launch).
__device__ float g_bufB[NFLOAT];   // x1
__device__ float g_bufC[NFLOAT];   // x2
__device__ float g_bufD[NFLOAT];   // x3

// ---------------------------------------------------------------------------
// Zero all three scatter targets in one pass (write-only, 230 MB).
// ---------------------------------------------------------------------------
__global__ void k_zero3(float4* __restrict__ b,
                        float4* __restrict__ c,
                        float4* __restrict__ d) {
    long i = (long)blockIdx.x * blockDim.x + threadIdx.x;
    if (i >= N4) return;
    const float4 z = make_float4(0.f, 0.f, 0.f, 0.f);
    b[i] = z; c[i] = z; d[i] = z;
}

// ---------------------------------------------------------------------------
// Half-dimension scatter, layer 1: gathers directly from the two input
// embedding tables (no concat copy). 8 lanes/edge, float4/lane, chunk
// offset c0 in {0, 8}. red.global.add.v4.f32 = 1 LTS op per 16 B.
// ---------------------------------------------------------------------------
__global__ void k_scatter_in(const float4* __restrict__ user4,
                             const float4* __restrict__ item4,
                             float4*       __restrict__ y4,
                             const int*    __restrict__ esrc,
                             const int*    __restrict__ edst,
                             const float*  __restrict__ eval,
                             int c0) {
    long t = (long)blockIdx.x * blockDim.x + threadIdx.x;
    long e = t >> 3;
    int  c = (int)(t & 7) + c0;
    if (e >= NUM_EDGES) return;

    int   s = esrc[e];
    int   d = edst[e];
    float v = eval[e];

    const float4* row = (d < NUM_USERS) ? (user4 + (long)d * 16)
                                        : (item4 + (long)(d - NUM_USERS) * 16);
    float4 m = __ldg(row + c);
    m.x *= v; m.y *= v; m.z *= v; m.w *= v;

    float4* addr = y4 + (long)s * 16 + c;
    asm volatile("red.global.add.v4.f32 [%0], {%1, %2, %3, %4};"
                 :: "l"(addr), "f"(m.x), "f"(m.y), "f"(m.z), "f"(m.w)
                 : "memory");
}

// ---------------------------------------------------------------------------
// Half-dimension scatter, layers 2-3: x4 is a full node-feature buffer.
// Per half-pass the touched footprint is 38.4 MB (x) + 38.4 MB (y): L2-resident.
// ---------------------------------------------------------------------------
__global__ void k_scatter(const float4* __restrict__ x4,
                          float4*       __restrict__ y4,
                          const int*    __restrict__ esrc,
                          const int*    __restrict__ edst,
                          const float*  __restrict__ eval,
                          int c0) {
    long t = (long)blockIdx.x * blockDim.x + threadIdx.x;
    long e = t >> 3;
    int  c = (int)(t & 7) + c0;
    if (e >= NUM_EDGES) return;

    int   s = esrc[e];
    int   d = edst[e];
    float v = eval[e];

    float4 m = __ldg(x4 + (long)d * 16 + c);
    m.x *= v; m.y *= v; m.z *= v; m.w *= v;

    float4* addr = y4 + (long)s * 16 + c;
    asm volatile("red.global.add.v4.f32 [%0], {%1, %2, %3, %4};"
                 :: "l"(addr), "f"(m.x), "f"(m.y), "f"(m.z), "f"(m.w)
                 : "memory");
}

// ---------------------------------------------------------------------------
// Final: out = (x0 + x1 + x2 + x3) / 4, x0 read straight from the inputs.
// ---------------------------------------------------------------------------
__global__ void k_final(const float4* __restrict__ user4,
                        const float4* __restrict__ item4,
                        const float4* __restrict__ b,
                        const float4* __restrict__ c,
                        const float4* __restrict__ d,
                        float4*       __restrict__ out4) {
    long i = (long)blockIdx.x * blockDim.x + threadIdx.x;
    if (i >= N4) return;
    const long uf4 = (long)NUM_USERS * DIM / 4;
    float4 a = (i < uf4) ? user4[i] : item4[i - uf4];
    float4 vb = b[i], vc = c[i], vd = d[i];
    a.x = (a.x + vb.x + vc.x + vd.x) * 0.25f;
    a.y = (a.y + vb.y + vc.y + vd.y) * 0.25f;
    a.z = (a.z + vb.z + vc.z + vd.z) * 0.25f;
    a.w = (a.w + vb.w + vc.w + vd.w) * 0.25f;
    out4[i] = a;
}

extern "C" void kernel_launch(void* const* d_in, const int* in_sizes, int n_in,
                              void* d_out, int out_size) {
    const float4* user4 = (const float4*)d_in[0];
    const float4* item4 = (const float4*)d_in[1];
    const float*  eval  = (const float*) d_in[2];
    const int*    esrc  = (const int*)   d_in[3];
    const int*    edst  = (const int*)   d_in[4];
    float4*       out4  = (float4*)d_out;

    void *pB, *pC, *pD;
    cudaGetSymbolAddress(&pB, g_bufB);
    cudaGetSymbolAddress(&pC, g_bufC);
    cudaGetSymbolAddress(&pD, g_bufD);
    float4* B = (float4*)pB;
    float4* C = (float4*)pC;
    float4* D = (float4*)pD;

    const int TB = 256;
    const unsigned elem_blocks    = (unsigned)((N4 + TB - 1) / TB);                 // 18750
    const unsigned scatter_blocks = (unsigned)(((long)NUM_EDGES * 8 + TB - 1) / TB); // 62500

    k_zero3<<<elem_blocks, TB>>>(B, C, D);

    // Layer 1: inputs -> B   (two L2-resident half passes)
    k_scatter_in<<<scatter_blocks, TB>>>(user4, item4, B, esrc, edst, eval, 0);
    k_scatter_in<<<scatter_blocks, TB>>>(user4, item4, B, esrc, edst, eval, 8);

    // Layer 2: B -> C
    k_scatter<<<scatter_blocks, TB>>>(B, C, esrc, edst, eval, 0);
    k_scatter<<<scatter_blocks, TB>>>(B, C, esrc, edst, eval, 8);

    // Layer 3: C -> D
    k_scatter<<<scatter_blocks, TB>>>(C, D, esrc, edst, eval, 0);
    k_scatter<<<scatter_blocks, TB>>>(C, D, esrc, edst, eval, 8);

    // out = (x0 + B + C + D) / 4
    k_final<<<elem_blocks, TB>>>(user4, item4, B, C, D, out4);
}

// round 4
// speedup vs baseline: 1.8918x; 1.5399x over previous
#include <cuda_runtime.h>
#include <cstdint>

#define NUM_USERS 100000
#define NUM_ITEMS 200000
#define NUM_NODES (NUM_USERS + NUM_ITEMS)
#define DIM 64
#define NUM_EDGES 2000000
#define NFLOAT ((long)NUM_NODES * DIM)        // 19,200,000 floats
#define N4 (NFLOAT / 4)

#define SCAN_BS 512
#define SCAN_NB ((NUM_NODES + SCAN_BS - 1) / SCAN_BS)   // 586 (must be <= 1024)

// ---- device-global scratch (allocation in kernel_launch is forbidden) ----
__device__ float g_bufB[NFLOAT];             // x1
__device__ float g_bufC[NFLOAT];             // x2
__device__ int2  g_edges[NUM_EDGES];         // sorted-by-src {dst, val bits}
__device__ int   g_counts[NUM_NODES];
__device__ int   g_off[NUM_NODES];
__device__ int   g_cursor[NUM_NODES];
__device__ int   g_bsums[SCAN_NB];

// ===========================================================================
// Counting-sort stage
// ===========================================================================
__global__ void k_zero_cc() {
    int i = blockIdx.x * blockDim.x + threadIdx.x;
    if (i < NUM_NODES) { g_counts[i] = 0; g_cursor[i] = 0; }
}

__global__ void k_hist(const int* __restrict__ esrc) {
    int e = blockIdx.x * blockDim.x + threadIdx.x;
    if (e < NUM_EDGES) atomicAdd(&g_counts[esrc[e]], 1);
}

__global__ void k_scan1() {
    __shared__ int sm[SCAN_BS];
    int i = blockIdx.x * SCAN_BS + threadIdx.x;
    int v = (i < NUM_NODES) ? g_counts[i] : 0;
    sm[threadIdx.x] = v; __syncthreads();
    #pragma unroll
    for (int ofs = 1; ofs < SCAN_BS; ofs <<= 1) {
        int t = (threadIdx.x >= ofs) ? sm[threadIdx.x - ofs] : 0;
        __syncthreads();
        sm[threadIdx.x] += t;
        __syncthreads();
    }
    if (i < NUM_NODES) g_off[i] = sm[threadIdx.x] - v;     // exclusive
    if (threadIdx.x == SCAN_BS - 1) g_bsums[blockIdx.x] = sm[threadIdx.x];
}

__global__ void k_scan2() {   // single block of 1024 threads
    __shared__ int sm[1024];
    int v = (threadIdx.x < SCAN_NB) ? g_bsums[threadIdx.x] : 0;
    sm[threadIdx.x] = v; __syncthreads();
    #pragma unroll
    for (int ofs = 1; ofs < 1024; ofs <<= 1) {
        int t = (threadIdx.x >= ofs) ? sm[threadIdx.x - ofs] : 0;
        __syncthreads();
        sm[threadIdx.x] += t;
        __syncthreads();
    }
    if (threadIdx.x < SCAN_NB) g_bsums[threadIdx.x] = sm[threadIdx.x] - v;  // exclusive
}

__global__ void k_scan3() {
    int i = blockIdx.x * SCAN_BS + threadIdx.x;
    if (i < NUM_NODES) g_off[i] += g_bsums[blockIdx.x];
}

__global__ void k_reorder(const int* __restrict__ esrc,
                          const int* __restrict__ edst,
                          const float* __restrict__ eval) {
    int e = blockIdx.x * blockDim.x + threadIdx.x;
    if (e >= NUM_EDGES) return;
    int s = esrc[e];
    int p = g_off[s] + atomicAdd(&g_cursor[s], 1);
    g_edges[p] = make_int2(edst[e], __float_as_int(eval[e]));
}

// ===========================================================================
// Segmented-sum layers: 8 lanes per node; each lane owns chunks l and l+8
// (two float4 accumulators = full 64-dim row). One plain streamed store per
// chunk — NO atomics.
// ===========================================================================
__device__ __forceinline__ void acc_row(const float4* __restrict__ row,
                                        int l, float v,
                                        float4& a0, float4& a1) {
    float4 m0 = __ldg(row + l);
    float4 m1 = __ldg(row + l + 8);
    a0.x += m0.x * v; a0.y += m0.y * v; a0.z += m0.z * v; a0.w += m0.w * v;
    a1.x += m1.x * v; a1.y += m1.y * v; a1.z += m1.z * v; a1.w += m1.w * v;
}

// Layer 1: gather directly from the input embedding tables -> B
__global__ void k_layer1(const float4* __restrict__ user4,
                         const float4* __restrict__ item4,
                         float4* __restrict__ y4) {
    long t = (long)blockIdx.x * blockDim.x + threadIdx.x;
    long n = t >> 3;
    int  l = (int)(t & 7);
    if (n >= NUM_NODES) return;

    int beg = g_off[n];
    int end = beg + g_counts[n];
    float4 a0 = make_float4(0.f, 0.f, 0.f, 0.f), a1 = a0;
    for (int p = beg; p < end; ++p) {
        int2 ed = __ldg(&g_edges[p]);
        int d = ed.x; float v = __int_as_float(ed.y);
        const float4* row = (d < NUM_USERS) ? (user4 + (long)d * 16)
                                            : (item4 + (long)(d - NUM_USERS) * 16);
        acc_row(row, l, v, a0, a1);
    }
    __stcs(y4 + n * 16 + l,     a0);
    __stcs(y4 + n * 16 + 8 + l, a1);
}

// Layer 2: gather from full node buffer -> C
__global__ void k_layer_mid(const float4* __restrict__ x4,
                            float4* __restrict__ y4) {
    long t = (long)blockIdx.x * blockDim.x + threadIdx.x;
    long n = t >> 3;
    int  l = (int)(t & 7);
    if (n >= NUM_NODES) return;

    int beg = g_off[n];
    int end = beg + g_counts[n];
    float4 a0 = make_float4(0.f, 0.f, 0.f, 0.f), a1 = a0;
    for (int p = beg; p < end; ++p) {
        int2 ed = __ldg(&g_edges[p]);
        acc_row(x4 + (long)ed.x * 16, l, __int_as_float(ed.y), a0, a1);
    }
    __stcs(y4 + n * 16 + l,     a0);
    __stcs(y4 + n * 16 + 8 + l, a1);
}

// Layer 3 + fused epilogue: out = (x0 + B + C + x3) / 4
__global__ void k_layer3_final(const float4* __restrict__ x4,     // C (= x2)
                               const float4* __restrict__ user4,
                               const float4* __restrict__ item4,
                               const float4* __restrict__ b4,     // B (= x1)
                               float4* __restrict__ out4) {
    long t = (long)blockIdx.x * blockDim.x + threadIdx.x;
    long n = t >> 3;
    int  l = (int)(t & 7);
    if (n >= NUM_NODES) return;

    int beg = g_off[n];
    int end = beg + g_counts[n];
    float4 a0 = make_float4(0.f, 0.f, 0.f, 0.f), a1 = a0;
    for (int p = beg; p < end; ++p) {
        int2 ed = __ldg(&g_edges[p]);
        acc_row(x4 + (long)ed.x * 16, l, __int_as_float(ed.y), a0, a1);
    }

    const float4* x0 = (n < NUM_USERS) ? (user4 + n * 16)
                                       : (item4 + (n - NUM_USERS) * 16);
    float4 e0 = __ldg(x0 + l),            e1 = __ldg(x0 + 8 + l);
    float4 b0 = __ldg(b4 + n * 16 + l),   b1 = __ldg(b4 + n * 16 + 8 + l);
    float4 c0 = __ldg(x4 + n * 16 + l),   c1 = __ldg(x4 + n * 16 + 8 + l);

    a0.x = (a0.x + e0.x + b0.x + c0.x) * 0.25f;
    a0.y = (a0.y + e0.y + b0.y + c0.y) * 0.25f;
    a0.z = (a0.z + e0.z + b0.z + c0.z) * 0.25f;
    a0.w = (a0.w + e0.w + b0.w + c0.w) * 0.25f;
    a1.x = (a1.x + e1.x + b1.x + c1.x) * 0.25f;
    a1.y = (a1.y + e1.y + b1.y + c1.y) * 0.25f;
    a1.z = (a1.z + e1.z + b1.z + c1.z) * 0.25f;
    a1.w = (a1.w + e1.w + b1.w + c1.w) * 0.25f;

    __stcs(out4 + n * 16 + l,     a0);
    __stcs(out4 + n * 16 + 8 + l, a1);
}

// ===========================================================================
extern "C" void kernel_launch(void* const* d_in, const int* in_sizes, int n_in,
                              void* d_out, int out_size) {
    const float4* user4 = (const float4*)d_in[0];
    const float4* item4 = (const float4*)d_in[1];
    const float*  eval  = (const float*) d_in[2];
    const int*    esrc  = (const int*)   d_in[3];
    const int*    edst  = (const int*)   d_in[4];
    float4*       out4  = (float4*)d_out;

    void *pB, *pC;
    cudaGetSymbolAddress(&pB, g_bufB);
    cudaGetSymbolAddress(&pC, g_bufC);
    float4* B = (float4*)pB;
    float4* C = (float4*)pC;

    const int TB = 256;
    const unsigned node_blocks  = (NUM_NODES + TB - 1) / TB;                    // 1172
    const unsigned edge_blocks  = (NUM_EDGES + TB - 1) / TB;                    // 7813
    const unsigned group_blocks = (unsigned)(((long)NUM_NODES * 8 + TB - 1) / TB); // 9375

    // --- counting sort of edges by src ---
    k_zero_cc<<<node_blocks, TB>>>();
    k_hist   <<<edge_blocks, TB>>>(esrc);
    k_scan1  <<<SCAN_NB, SCAN_BS>>>();
    k_scan2  <<<1, 1024>>>();
    k_scan3  <<<SCAN_NB, SCAN_BS>>>();
    k_reorder<<<edge_blocks, TB>>>(esrc, edst, eval);

    // --- 3 propagation layers (segmented sums, no atomics) ---
    k_layer1      <<<group_blocks, TB>>>(user4, item4, B);
    k_layer_mid   <<<group_blocks, TB>>>(B, C);
    k_layer3_final<<<group_blocks, TB>>>(C, user4, item4, B, out4);
}

// round 5
// speedup vs baseline: 2.5124x; 1.3280x over previous
#include <cuda_runtime.h>
#include <cuda_fp16.h>
#include <cstdint>

#define NUM_USERS 100000
#define NUM_ITEMS 200000
#define NUM_NODES (NUM_USERS + NUM_ITEMS)
#define DIM 64
#define NUM_EDGES 2000000
#define NFLOAT ((long)NUM_NODES * DIM)

#define SCAN_BS 512
#define SCAN_NB ((NUM_NODES + SCAN_BS - 1) / SCAN_BS)   // 586
#define DEG_BINS 64

// ---- device-global scratch ----
__device__ __half g_bufB[NFLOAT];            // x1 (fp16)
__device__ __half g_bufC[NFLOAT];            // x2 (fp16)
__device__ int2   g_edges[NUM_EDGES];        // sorted-by-src {dst, val bits}
__device__ int    g_counts[NUM_NODES];
__device__ int    g_off[NUM_NODES];
__device__ int    g_cursor[NUM_NODES];
__device__ int    g_bsums[SCAN_NB];
__device__ int    g_perm[NUM_NODES];         // nodes sorted by degree
__device__ int    g_deghist[DEG_BINS];
__device__ int    g_degcursor[DEG_BINS];

// ===========================================================================
// Counting-sort of edges by src + degree-bucketed node permutation
// ===========================================================================
__global__ void k_zero_cc() {
    int i = blockIdx.x * blockDim.x + threadIdx.x;
    if (i < NUM_NODES) { g_counts[i] = 0; g_cursor[i] = 0; }
    if (i < DEG_BINS)  g_deghist[i] = 0;
}

__global__ void k_hist(const int* __restrict__ esrc) {
    int e = blockIdx.x * blockDim.x + threadIdx.x;
    if (e < NUM_EDGES) atomicAdd(&g_counts[esrc[e]], 1);
}

__global__ void k_scan1() {
    __shared__ int sm[SCAN_BS];
    int i = blockIdx.x * SCAN_BS + threadIdx.x;
    int v = (i < NUM_NODES) ? g_counts[i] : 0;
    sm[threadIdx.x] = v; __syncthreads();
    #pragma unroll
    for (int ofs = 1; ofs < SCAN_BS; ofs <<= 1) {
        int t = (threadIdx.x >= ofs) ? sm[threadIdx.x - ofs] : 0;
        __syncthreads();
        sm[threadIdx.x] += t;
        __syncthreads();
    }
    if (i < NUM_NODES) g_off[i] = sm[threadIdx.x] - v;     // exclusive
    if (threadIdx.x == SCAN_BS - 1) g_bsums[blockIdx.x] = sm[threadIdx.x];
}

__global__ void k_scan2() {   // one block, 1024 threads
    __shared__ int sm[1024];
    int v = (threadIdx.x < SCAN_NB) ? g_bsums[threadIdx.x] : 0;
    sm[threadIdx.x] = v; __syncthreads();
    #pragma unroll
    for (int ofs = 1; ofs < 1024; ofs <<= 1) {
        int t = (threadIdx.x >= ofs) ? sm[threadIdx.x - ofs] : 0;
        __syncthreads();
        sm[threadIdx.x] += t;
        __syncthreads();
    }
    if (threadIdx.x < SCAN_NB) g_bsums[threadIdx.x] = sm[threadIdx.x] - v;
}

__global__ void k_scan3() {
    int i = blockIdx.x * SCAN_BS + threadIdx.x;
    if (i < NUM_NODES) g_off[i] += g_bsums[blockIdx.x];
}

__global__ void k_reorder(const int* __restrict__ esrc,
                          const int* __restrict__ edst,
                          const float* __restrict__ eval) {
    int e = blockIdx.x * blockDim.x + threadIdx.x;
    if (e >= NUM_EDGES) return;
    int s = esrc[e];
    int p = g_off[s] + atomicAdd(&g_cursor[s], 1);
    g_edges[p] = make_int2(edst[e], __float_as_int(eval[e]));
}

// ---- degree bucketing: group equal-degree nodes into the same warps ----
__global__ void k_deghist() {
    __shared__ int sh[DEG_BINS];
    if (threadIdx.x < DEG_BINS) sh[threadIdx.x] = 0;
    __syncthreads();
    int i = blockIdx.x * blockDim.x + threadIdx.x;
    if (i < NUM_NODES) {
        int d = g_counts[i]; if (d > DEG_BINS - 1) d = DEG_BINS - 1;
        atomicAdd(&sh[d], 1);
    }
    __syncthreads();
    if (threadIdx.x < DEG_BINS && sh[threadIdx.x])
        atomicAdd(&g_deghist[threadIdx.x], sh[threadIdx.x]);
}

__global__ void k_degscan() {   // 1 block, 64 threads
    __shared__ int sm[DEG_BINS];
    sm[threadIdx.x] = g_deghist[threadIdx.x];
    __syncthreads();
    if (threadIdx.x == 0) {
        int acc = 0;
        for (int i = 0; i < DEG_BINS; ++i) { int c = sm[i]; sm[i] = acc; acc += c; }
    }
    __syncthreads();
    g_degcursor[threadIdx.x] = sm[threadIdx.x];
}

__global__ void k_permute() {
    __shared__ int s_hist[DEG_BINS];
    __shared__ int s_base[DEG_BINS];
    if (threadIdx.x < DEG_BINS) s_hist[threadIdx.x] = 0;
    __syncthreads();
    int i = blockIdx.x * blockDim.x + threadIdx.x;
    int bin = 0, rank = 0;
    if (i < NUM_NODES) {
        int d = g_counts[i]; bin = (d > DEG_BINS - 1) ? DEG_BINS - 1 : d;
        rank = atomicAdd(&s_hist[bin], 1);
    }
    __syncthreads();
    if (threadIdx.x < DEG_BINS)
        s_base[threadIdx.x] = atomicAdd(&g_degcursor[threadIdx.x], s_hist[threadIdx.x]);
    __syncthreads();
    if (i < NUM_NODES) g_perm[s_base[bin] + rank] = i;
}

// ===========================================================================
// Segmented-sum layers. 8 lanes per node; lane l owns dims [8l .. 8l+7],
// accumulated in fp32. fp16 rows are one coalesced uint4 per lane.
// ===========================================================================
__device__ __forceinline__ void acc_h8(uint4 r, float v, float* a) {
    float2 f;
    f = __half22float2(*(const __half2*)&r.x); a[0] += f.x * v; a[1] += f.y * v;
    f = __half22float2(*(const __half2*)&r.y); a[2] += f.x * v; a[3] += f.y * v;
    f = __half22float2(*(const __half2*)&r.z); a[4] += f.x * v; a[5] += f.y * v;
    f = __half22float2(*(const __half2*)&r.w); a[6] += f.x * v; a[7] += f.y * v;
}

__device__ __forceinline__ uint4 pack_h8(const float* a) {
    uint4 o;
    *(__half2*)&o.x = __floats2half2_rn(a[0], a[1]);
    *(__half2*)&o.y = __floats2half2_rn(a[2], a[3]);
    *(__half2*)&o.z = __floats2half2_rn(a[4], a[5]);
    *(__half2*)&o.w = __floats2half2_rn(a[6], a[7]);
    return o;
}

// Layer 1: gather fp32 inputs -> fp16 B
__global__ void k_layer1(const float4* __restrict__ user4,
                         const float4* __restrict__ item4,
                         uint4* __restrict__ y) {
    long t = (long)blockIdx.x * blockDim.x + threadIdx.x;
    long g = t >> 3;
    int  l = (int)(t & 7);
    if (g >= NUM_NODES) return;
    int n = g_perm[g];
    int beg = g_off[n], end = beg + g_counts[n];

    float a[8] = {0.f,0.f,0.f,0.f,0.f,0.f,0.f,0.f};
    if (beg < end) {
        int2 e0 = __ldg(&g_edges[beg]);
        for (int p = beg + 1; p < end; ++p) {
            int2 e1 = __ldg(&g_edges[p]);   // prefetch next edge
            int d = e0.x; float v = __int_as_float(e0.y);
            const float4* row = (d < NUM_USERS) ? (user4 + (long)d * 16)
                                                : (item4 + (long)(d - NUM_USERS) * 16);
            float4 m0 = __ldg(row + 2 * l);
            float4 m1 = __ldg(row + 2 * l + 1);
            a[0]+=m0.x*v; a[1]+=m0.y*v; a[2]+=m0.z*v; a[3]+=m0.w*v;
            a[4]+=m1.x*v; a[5]+=m1.y*v; a[6]+=m1.z*v; a[7]+=m1.w*v;
            e0 = e1;
        }
        int d = e0.x; float v = __int_as_float(e0.y);
        const float4* row = (d < NUM_USERS) ? (user4 + (long)d * 16)
                                            : (item4 + (long)(d - NUM_USERS) * 16);
        float4 m0 = __ldg(row + 2 * l);
        float4 m1 = __ldg(row + 2 * l + 1);
        a[0]+=m0.x*v; a[1]+=m0.y*v; a[2]+=m0.z*v; a[3]+=m0.w*v;
        a[4]+=m1.x*v; a[5]+=m1.y*v; a[6]+=m1.z*v; a[7]+=m1.w*v;
    }
    __stcs(y + (long)n * 8 + l, pack_h8(a));
}

// Layer 2: gather fp16 -> fp16
__global__ void k_layer_mid(const uint4* __restrict__ x,
                            uint4* __restrict__ y) {
    long t = (long)blockIdx.x * blockDim.x + threadIdx.x;
    long g = t >> 3;
    int  l = (int)(t & 7);
    if (g >= NUM_NODES) return;
    int n = g_perm[g];
    int beg = g_off[n], end = beg + g_counts[n];

    float a[8] = {0.f,0.f,0.f,0.f,0.f,0.f,0.f,0.f};
    if (beg < end) {
        int2 e0 = __ldg(&g_edges[beg]);
        uint4 r0 = __ldg(x + (long)e0.x * 8 + l);
        for (int p = beg + 1; p < end; ++p) {
            int2 e1 = __ldg(&g_edges[p]);
            uint4 r1 = __ldg(x + (long)e1.x * 8 + l);
            acc_h8(r0, __int_as_float(e0.y), a);
            e0 = e1; r0 = r1;
        }
        acc_h8(r0, __int_as_float(e0.y), a);
    }
    __stcs(y + (long)n * 8 + l, pack_h8(a));
}

// Layer 3 + fused epilogue: out = (x0 + B + C + x3) / 4   (fp32 out)
__global__ void k_layer3_final(const uint4* __restrict__ x,      // C (x2)
                               const float4* __restrict__ user4,
                               const float4* __restrict__ item4,
                               const uint4* __restrict__ b,      // B (x1)
                               float4* __restrict__ out4) {
    long t = (long)blockIdx.x * blockDim.x + threadIdx.x;
    long g = t >> 3;
    int  l = (int)(t & 7);
    if (g >= NUM_NODES) return;
    int n = g_perm[g];
    int beg = g_off[n], end = beg + g_counts[n];

    float a[8] = {0.f,0.f,0.f,0.f,0.f,0.f,0.f,0.f};
    if (beg < end) {
        int2 e0 = __ldg(&g_edges[beg]);
        uint4 r0 = __ldg(x + (long)e0.x * 8 + l);
        for (int p = beg + 1; p < end; ++p) {
            int2 e1 = __ldg(&g_edges[p]);
            uint4 r1 = __ldg(x + (long)e1.x * 8 + l);
            acc_h8(r0, __int_as_float(e0.y), a);
            e0 = e1; r0 = r1;
        }
        acc_h8(r0, __int_as_float(e0.y), a);
    }

    // epilogue: add x0 (fp32 inputs), x1 (B fp16), x2 (C fp16), scale by 1/4
    const float4* x0 = (n < NUM_USERS) ? (user4 + (long)n * 16)
                                       : (item4 + (long)(n - NUM_USERS) * 16);
    float4 e0 = __ldg(x0 + 2 * l);
    float4 e1 = __ldg(x0 + 2 * l + 1);
    uint4 br = __ldg(b + (long)n * 8 + l);
    uint4 cr = __ldg(x + (long)n * 8 + l);
    float bb[8], cc[8];
    {
        float2 f;
        f = __half22float2(*(const __half2*)&br.x); bb[0]=f.x; bb[1]=f.y;
        f = __half22float2(*(const __half2*)&br.y); bb[2]=f.x; bb[3]=f.y;
        f = __half22float2(*(const __half2*)&br.z); bb[4]=f.x; bb[5]=f.y;
        f = __half22float2(*(const __half2*)&br.w); bb[6]=f.x; bb[7]=f.y;
        f = __half22float2(*(const __half2*)&cr.x); cc[0]=f.x; cc[1]=f.y;
        f = __half22float2(*(const __half2*)&cr.y); cc[2]=f.x; cc[3]=f.y;
        f = __half22float2(*(const __half2*)&cr.z); cc[4]=f.x; cc[5]=f.y;
        f = __half22float2(*(const __half2*)&cr.w); cc[6]=f.x; cc[7]=f.y;
    }
    float4 o0, o1;
    o0.x = (a[0] + e0.x + bb[0] + cc[0]) * 0.25f;
    o0.y = (a[1] + e0.y + bb[1] + cc[1]) * 0.25f;
    o0.z = (a[2] + e0.z + bb[2] + cc[2]) * 0.25f;
    o0.w = (a[3] + e0.w + bb[3] + cc[3]) * 0.25f;
    o1.x = (a[4] + e1.x + bb[4] + cc[4]) * 0.25f;
    o1.y = (a[5] + e1.y + bb[5] + cc[5]) * 0.25f;
    o1.z = (a[6] + e1.z + bb[6] + cc[6]) * 0.25f;
    o1.w = (a[7] + e1.w + bb[7] + cc[7]) * 0.25f;
    __stcs(out4 + (long)n * 16 + 2 * l,     o0);
    __stcs(out4 + (long)n * 16 + 2 * l + 1, o1);
}

// ===========================================================================
extern "C" void kernel_launch(void* const* d_in, const int* in_sizes, int n_in,
                              void* d_out, int out_size) {
    const float4* user4 = (const float4*)d_in[0];
    const float4* item4 = (const float4*)d_in[1];
    const float*  eval  = (const float*) d_in[2];
    const int*    esrc  = (const int*)   d_in[3];
    const int*    edst  = (const int*)   d_in[4];
    float4*       out4  = (float4*)d_out;

    void *pB, *pC;
    cudaGetSymbolAddress(&pB, g_bufB);
    cudaGetSymbolAddress(&pC, g_bufC);
    uint4* B = (uint4*)pB;
    uint4* C = (uint4*)pC;

    const int TB = 256;
    const unsigned node_blocks  = (NUM_NODES + TB - 1) / TB;                       // 1172
    const unsigned edge_blocks  = (NUM_EDGES + TB - 1) / TB;                       // 7813
    const unsigned group_blocks = (unsigned)(((long)NUM_NODES * 8 + TB - 1) / TB); // 9375

    // --- sort edges by src; build degree-bucketed node permutation ---
    k_zero_cc<<<node_blocks, TB>>>();
    k_hist   <<<edge_blocks, TB>>>(esrc);
    k_scan1  <<<SCAN_NB, SCAN_BS>>>();
    k_scan2  <<<1, 1024>>>();
    k_scan3  <<<SCAN_NB, SCAN_BS>>>();
    k_reorder<<<edge_blocks, TB>>>(esrc, edst, eval);
    k_deghist<<<node_blocks, TB>>>();
    k_degscan<<<1, DEG_BINS>>>();
    k_permute<<<node_blocks, TB>>>();

    // --- 3 propagation layers (segmented sums, degree-uniform warps) ---
    k_layer1      <<<group_blocks, TB>>>(user4, item4, B);
    k_layer_mid   <<<group_blocks, TB>>>(B, C);
    k_layer3_final<<<group_blocks, TB>>>(C, user4, item4, B, out4);
}

// round 7
// speedup vs baseline: 2.6594x; 1.0585x over previous
#include <cuda_runtime.h>
#include <cuda_fp16.h>
#include <cstdint>

#define NUM_USERS 100000
#define NUM_ITEMS 200000
#define NUM_NODES (NUM_USERS + NUM_ITEMS)
#define DIM 64
#define NUM_EDGES 2000000
#define NFLOAT ((long)NUM_NODES * DIM)

#define SCAN_BS 512
#define SCAN_NB ((NUM_NODES + SCAN_BS - 1) / SCAN_BS)   // 586
#define DEG_BINS 64

// ---- device-global scratch ----
__device__ __half g_bufA[NFLOAT];            // x0 (fp16 copy of inputs)
__device__ __half g_bufB[NFLOAT];            // x1 (fp16)
__device__ __half g_bufC[NFLOAT];            // x2 (fp16)
__device__ int2   g_edges[NUM_EDGES];        // sorted-by-src {dst, val bits}
__device__ int    g_counts[NUM_NODES];
__device__ int    g_off[NUM_NODES];
__device__ int    g_cursor[NUM_NODES];
__device__ int    g_bsums[SCAN_NB];
__device__ int    g_perm[NUM_NODES];         // nodes grouped by degree
__device__ int    g_deghist[DEG_BINS];
__device__ int    g_degcursor[DEG_BINS];

// ===========================================================================
// Prep: convert x0 -> fp16 A (8 lanes/node) AND zero counters.
// ===========================================================================
__global__ void k_prep(const float4* __restrict__ user4,
                       const float4* __restrict__ item4,
                       uint4* __restrict__ a) {
    long t = (long)blockIdx.x * blockDim.x + threadIdx.x;
    if (t < NUM_NODES) { g_counts[t] = 0; g_cursor[t] = 0; }
    if (t < DEG_BINS)  g_deghist[t] = 0;

    long n = t >> 3;
    int  l = (int)(t & 7);
    if (n >= NUM_NODES) return;
    const float4* x0 = (n < NUM_USERS) ? (user4 + n * 16)
                                       : (item4 + (n - NUM_USERS) * 16);
    float4 m0 = __ldg(x0 + 2 * l);
    float4 m1 = __ldg(x0 + 2 * l + 1);
    uint4 o;
    *(__half2*)&o.x = __floats2half2_rn(m0.x, m0.y);
    *(__half2*)&o.y = __floats2half2_rn(m0.z, m0.w);
    *(__half2*)&o.z = __floats2half2_rn(m1.x, m1.y);
    *(__half2*)&o.w = __floats2half2_rn(m1.z, m1.w);
    __stcs(a + n * 8 + l, o);
}

__global__ void k_hist(const int* __restrict__ esrc) {
    int e = blockIdx.x * blockDim.x + threadIdx.x;
    if (e < NUM_EDGES) atomicAdd(&g_counts[esrc[e]], 1);
}

// Scan pass 1 + degree histogram (shared-mem staged)
__global__ void k_scan1() {
    __shared__ int sm[SCAN_BS];
    __shared__ int sh[DEG_BINS];
    if (threadIdx.x < DEG_BINS) sh[threadIdx.x] = 0;
    int i = blockIdx.x * SCAN_BS + threadIdx.x;
    int v = (i < NUM_NODES) ? g_counts[i] : 0;
    sm[threadIdx.x] = v; __syncthreads();
    if (i < NUM_NODES) {
        int bin = (v > DEG_BINS - 1) ? DEG_BINS - 1 : v;
        atomicAdd(&sh[bin], 1);
    }
    #pragma unroll
    for (int ofs = 1; ofs < SCAN_BS; ofs <<= 1) {
        int t = (threadIdx.x >= ofs) ? sm[threadIdx.x - ofs] : 0;
        __syncthreads();
        sm[threadIdx.x] += t;
        __syncthreads();
    }
    if (i < NUM_NODES) g_off[i] = sm[threadIdx.x] - v;     // exclusive
    if (threadIdx.x == SCAN_BS - 1) g_bsums[blockIdx.x] = sm[threadIdx.x];
    if (threadIdx.x < DEG_BINS && sh[threadIdx.x])
        atomicAdd(&g_deghist[threadIdx.x], sh[threadIdx.x]);
}

// Block 0: exclusive scan of block sums. Block 1: exclusive scan of deg hist.
__global__ void k_scan2() {
    if (blockIdx.x == 0) {
        __shared__ int sm[1024];
        int v = (threadIdx.x < SCAN_NB) ? g_bsums[threadIdx.x] : 0;
        sm[threadIdx.x] = v; __syncthreads();
        #pragma unroll
        for (int ofs = 1; ofs < 1024; ofs <<= 1) {
            int t = (threadIdx.x >= ofs) ? sm[threadIdx.x - ofs] : 0;
            __syncthreads();
            sm[threadIdx.x] += t;
            __syncthreads();
        }
        if (threadIdx.x < SCAN_NB) g_bsums[threadIdx.x] = sm[threadIdx.x] - v;
    } else {
        __shared__ int sm[DEG_BINS];
        if (threadIdx.x < DEG_BINS) sm[threadIdx.x] = g_deghist[threadIdx.x];
        __syncthreads();
        if (threadIdx.x == 0) {
            int acc = 0;
            for (int i = 0; i < DEG_BINS; ++i) { int c = sm[i]; sm[i] = acc; acc += c; }
        }
        __syncthreads();
        if (threadIdx.x < DEG_BINS) g_degcursor[threadIdx.x] = sm[threadIdx.x];
    }
}

// Scan pass 3 (add block offsets) + degree-bucket permutation, fused.
__global__ void k_scan3_permute() {
    __shared__ int s_hist[DEG_BINS];
    __shared__ int s_base[DEG_BINS];
    if (threadIdx.x < DEG_BINS) s_hist[threadIdx.x] = 0;
    __syncthreads();
    int i = blockIdx.x * SCAN_BS + threadIdx.x;
    int bin = 0, rank = 0;
    if (i < NUM_NODES) {
        g_off[i] += g_bsums[blockIdx.x];
        int d = g_counts[i]; bin = (d > DEG_BINS - 1) ? DEG_BINS - 1 : d;
        rank = atomicAdd(&s_hist[bin], 1);
    }
    __syncthreads();
    if (threadIdx.x < DEG_BINS)
        s_base[threadIdx.x] = atomicAdd(&g_degcursor[threadIdx.x], s_hist[threadIdx.x]);
    __syncthreads();
    if (i < NUM_NODES) g_perm[s_base[bin] + rank] = i;
}

__global__ void k_reorder(const int* __restrict__ esrc,
                          const int* __restrict__ edst,
                          const float* __restrict__ eval) {
    int e = blockIdx.x * blockDim.x + threadIdx.x;
    if (e >= NUM_EDGES) return;
    int s = esrc[e];
    int p = g_off[s] + atomicAdd(&g_cursor[s], 1);
    g_edges[p] = make_int2(edst[e], __float_as_int(eval[e]));
}

// ===========================================================================
// Segmented-sum layers: 8 lanes/node, fp32 accumulation, fp16 rows (1 uint4
// per lane), 1-deep software pipeline, plain streamed stores (no atomics).
// ===========================================================================
__device__ __forceinline__ void acc_h8(uint4 r, float v, float* a) {
    float2 f;
    f = __half22float2(*(const __half2*)&r.x); a[0] += f.x * v; a[1] += f.y * v;
    f = __half22float2(*(const __half2*)&r.y); a[2] += f.x * v; a[3] += f.y * v;
    f = __half22float2(*(const __half2*)&r.z); a[4] += f.x * v; a[5] += f.y * v;
    f = __half22float2(*(const __half2*)&r.w); a[6] += f.x * v; a[7] += f.y * v;
}

__device__ __forceinline__ uint4 pack_h8(const float* a) {
    uint4 o;
    *(__half2*)&o.x = __floats2half2_rn(a[0], a[1]);
    *(__half2*)&o.y = __floats2half2_rn(a[2], a[3]);
    *(__half2*)&o.z = __floats2half2_rn(a[4], a[5]);
    *(__half2*)&o.w = __floats2half2_rn(a[6], a[7]);
    return o;
}

// Generic layer: fp16 x -> fp16 y   (used for layers 1 and 2)
__global__ void k_layer(const uint4* __restrict__ x,
                        uint4* __restrict__ y) {
    long t = (long)blockIdx.x * blockDim.x + threadIdx.x;
    long g = t >> 3;
    int  l = (int)(t & 7);
    if (g >= NUM_NODES) return;
    int n = g_perm[g];
    int beg = g_off[n], end = beg + g_counts[n];

    float a[8] = {0.f,0.f,0.f,0.f,0.f,0.f,0.f,0.f};
    if (beg < end) {
        int2 e0 = __ldg(&g_edges[beg]);
        uint4 r0 = __ldg(x + (long)e0.x * 8 + l);
        for (int p = beg + 1; p < end; ++p) {
            int2 e1 = __ldg(&g_edges[p]);
            uint4 r1 = __ldg(x + (long)e1.x * 8 + l);
            acc_h8(r0, __int_as_float(e0.y), a);
            e0 = e1; r0 = r1;
        }
        acc_h8(r0, __int_as_float(e0.y), a);
    }
    __stcs(y + (long)n * 8 + l, pack_h8(a));
}

// Layer 3 + fused epilogue: out = (x0_fp32 + B + C + x3)/4
__global__ void k_layer3_final(const uint4* __restrict__ x,      // C (x2)
                               const float4* __restrict__ user4,
                               const float4* __restrict__ item4,
                               const uint4* __restrict__ b,      // B (x1)
                               float4* __restrict__ out4) {
    long t = (long)blockIdx.x * blockDim.x + threadIdx.x;
    long g = t >> 3;
    int  l = (int)(t & 7);
    if (g >= NUM_NODES) return;
    int n = g_perm[g];
    int beg = g_off[n], end = beg + g_counts[n];

    float a[8] = {0.f,0.f,0.f,0.f,0.f,0.f,0.f,0.f};
    if (beg < end) {
        int2 e0 = __ldg(&g_edges[beg]);
        uint4 r0 = __ldg(x + (long)e0.x * 8 + l);
        for (int p = beg + 1; p < end; ++p) {
            int2 e1 = __ldg(&g_edges[p]);
            uint4 r1 = __ldg(x + (long)e1.x * 8 + l);
            acc_h8(r0, __int_as_float(e0.y), a);
            e0 = e1; r0 = r1;
        }
        acc_h8(r0, __int_as_float(e0.y), a);
    }

    const float4* x0 = (n < NUM_USERS) ? (user4 + (long)n * 16)
                                       : (item4 + (long)(n - NUM_USERS) * 16);
    float4 e0 = __ldg(x0 + 2 * l);
    float4 e1 = __ldg(x0 + 2 * l + 1);
    uint4 br = __ldg(b + (long)n * 8 + l);
    uint4 cr = __ldg(x + (long)n * 8 + l);
    float bb[8], cc[8];
    {
        float2 f;
        f = __half22float2(*(const __half2*)&br.x); bb[0]=f.x; bb[1]=f.y;
        f = __half22float2(*(const __half2*)&br.y); bb[2]=f.x; bb[3]=f.y;
        f = __half22float2(*(const __half2*)&br.z); bb[4]=f.x; bb[5]=f.y;
        f = __half22float2(*(const __half2*)&br.w); bb[6]=f.x; bb[7]=f.y;
        f = __half22float2(*(const __half2*)&cr.x); cc[0]=f.x; cc[1]=f.y;
        f = __half22float2(*(const __half2*)&cr.y); cc[2]=f.x; cc[3]=f.y;
        f = __half22float2(*(const __half2*)&cr.z); cc[4]=f.x; cc[5]=f.y;
        f = __half22float2(*(const __half2*)&cr.w); cc[6]=f.x; cc[7]=f.y;
    }
    float4 o0, o1;
    o0.x = (a[0] + e0.x + bb[0] + cc[0]) * 0.25f;
    o0.y = (a[1] + e0.y + bb[1] + cc[1]) * 0.25f;
    o0.z = (a[2] + e0.z + bb[2] + cc[2]) * 0.25f;
    o0.w = (a[3] + e0.w + bb[3] + cc[3]) * 0.25f;
    o1.x = (a[4] + e1.x + bb[4] + cc[4]) * 0.25f;
    o1.y = (a[5] + e1.y + bb[5] + cc[5]) * 0.25f;
    o1.z = (a[6] + e1.z + bb[6] + cc[6]) * 0.25f;
    o1.w = (a[7] + e1.w + bb[7] + cc[7]) * 0.25f;
    __stcs(out4 + (long)n * 16 + 2 * l,     o0);
    __stcs(out4 + (long)n * 16 + 2 * l + 1, o1);
}

// ===========================================================================
extern "C" void kernel_launch(void* const* d_in, const int* in_sizes, int n_in,
                              void* d_out, int out_size) {
    const float4* user4 = (const float4*)d_in[0];
    const float4* item4 = (const float4*)d_in[1];
    const float*  eval  = (const float*) d_in[2];
    const int*    esrc  = (const int*)   d_in[3];
    const int*    edst  = (const int*)   d_in[4];
    float4*       out4  = (float4*)d_out;

    void *pA, *pB, *pC;
    cudaGetSymbolAddress(&pA, g_bufA);
    cudaGetSymbolAddress(&pB, g_bufB);
    cudaGetSymbolAddress(&pC, g_bufC);
    uint4* A = (uint4*)pA;
    uint4* B = (uint4*)pB;
    uint4* C = (uint4*)pC;

    const int TB = 256;
    const unsigned edge_blocks  = (NUM_EDGES + TB - 1) / TB;                       // 7813
    const unsigned group_blocks = (unsigned)(((long)NUM_NODES * 8 + TB - 1) / TB); // 9375

    // --- prep: x0->fp16 + zero counters; sort edges by src; degree perm ---
    k_prep         <<<group_blocks, TB>>>(user4, item4, A);
    k_hist         <<<edge_blocks, TB>>>(esrc);
    k_scan1        <<<SCAN_NB, SCAN_BS>>>();
    k_scan2        <<<2, 1024>>>();
    k_scan3_permute<<<SCAN_NB, SCAN_BS>>>();
    k_reorder      <<<edge_blocks, TB>>>(esrc, edst, eval);

    // --- 3 propagation layers ---
    k_layer       <<<group_blocks, TB>>>(A, B);
    k_layer       <<<group_blocks, TB>>>(B, C);
    k_layer3_final<<<group_blocks, TB>>>(C, user4, item4, B, out4);
}

// round 8
// speedup vs baseline: 2.7829x; 1.0464x over previous
#include <cuda_runtime.h>
#include <cuda_fp16.h>
#include <cstdint>

#define NUM_USERS 100000
#define NUM_ITEMS 200000
#define NUM_NODES (NUM_USERS + NUM_ITEMS)
#define DIM 64
#define NUM_EDGES 2000000
#define NFLOAT ((long)NUM_NODES * DIM)

#define SCAN_BS 512
#define SCAN_NB ((NUM_NODES + SCAN_BS - 1) / SCAN_BS)   // 586
#define DEG_BINS 64

// ---- device-global scratch ----
__device__ __half g_bufA[NFLOAT];            // x0 (fp16 copy of inputs)
__device__ __half g_bufB[NFLOAT];            // x1 (fp16)
__device__ __half g_bufC[NFLOAT];            // x2 (fp16)
__device__ int2   g_edges[NUM_EDGES];        // sorted-by-src {dst, val bits}
__device__ int    g_counts[NUM_NODES];
__device__ int    g_off[NUM_NODES];          // exclusive offsets; after reorder = segment END
__device__ int    g_bsums[SCAN_NB];
__device__ int    g_perm[NUM_NODES];         // nodes grouped by degree
__device__ int    g_deghist[DEG_BINS];
__device__ int    g_degcursor[DEG_BINS];

// ===========================================================================
// Prep: convert x0 -> fp16 A (8 lanes/node) AND build src-degree histogram
// (g_counts zeroed beforehand via cudaMemsetAsync).
// ===========================================================================
__global__ void k_prep_hist(const float4* __restrict__ user4,
                            const float4* __restrict__ item4,
                            uint4* __restrict__ a,
                            const int* __restrict__ esrc) {
    long t = (long)blockIdx.x * blockDim.x + threadIdx.x;
    if (t < NUM_EDGES) atomicAdd(&g_counts[esrc[t]], 1);

    long n = t >> 3;
    int  l = (int)(t & 7);
    if (n >= NUM_NODES) return;
    const float4* x0 = (n < NUM_USERS) ? (user4 + n * 16)
                                       : (item4 + (n - NUM_USERS) * 16);
    float4 m0 = __ldg(x0 + 2 * l);
    float4 m1 = __ldg(x0 + 2 * l + 1);
    uint4 o;
    *(__half2*)&o.x = __floats2half2_rn(m0.x, m0.y);
    *(__half2*)&o.y = __floats2half2_rn(m0.z, m0.w);
    *(__half2*)&o.z = __floats2half2_rn(m1.x, m1.y);
    *(__half2*)&o.w = __floats2half2_rn(m1.z, m1.w);
    __stcs(a + n * 8 + l, o);
}

// Scan pass 1 + degree histogram
__global__ void k_scan1() {
    __shared__ int sm[SCAN_BS];
    __shared__ int sh[DEG_BINS];
    if (threadIdx.x < DEG_BINS) sh[threadIdx.x] = 0;
    int i = blockIdx.x * SCAN_BS + threadIdx.x;
    int v = (i < NUM_NODES) ? g_counts[i] : 0;
    sm[threadIdx.x] = v; __syncthreads();
    if (i < NUM_NODES) {
        int bin = (v > DEG_BINS - 1) ? DEG_BINS - 1 : v;
        atomicAdd(&sh[bin], 1);
    }
    #pragma unroll
    for (int ofs = 1; ofs < SCAN_BS; ofs <<= 1) {
        int t = (threadIdx.x >= ofs) ? sm[threadIdx.x - ofs] : 0;
        __syncthreads();
        sm[threadIdx.x] += t;
        __syncthreads();
    }
    if (i < NUM_NODES) g_off[i] = sm[threadIdx.x] - v;     // exclusive
    if (threadIdx.x == SCAN_BS - 1) g_bsums[blockIdx.x] = sm[threadIdx.x];
    if (threadIdx.x < DEG_BINS && sh[threadIdx.x])
        atomicAdd(&g_deghist[threadIdx.x], sh[threadIdx.x]);
}

// Block 0: scan of block sums. Block 1: scan of degree histogram.
__global__ void k_scan2() {
    if (blockIdx.x == 0) {
        __shared__ int sm[1024];
        int v = (threadIdx.x < SCAN_NB) ? g_bsums[threadIdx.x] : 0;
        sm[threadIdx.x] = v; __syncthreads();
        #pragma unroll
        for (int ofs = 1; ofs < 1024; ofs <<= 1) {
            int t = (threadIdx.x >= ofs) ? sm[threadIdx.x - ofs] : 0;
            __syncthreads();
            sm[threadIdx.x] += t;
            __syncthreads();
        }
        if (threadIdx.x < SCAN_NB) g_bsums[threadIdx.x] = sm[threadIdx.x] - v;
    } else {
        __shared__ int sm[DEG_BINS];
        if (threadIdx.x < DEG_BINS) sm[threadIdx.x] = g_deghist[threadIdx.x];
        __syncthreads();
        if (threadIdx.x == 0) {
            int acc = 0;
            for (int i = 0; i < DEG_BINS; ++i) { int c = sm[i]; sm[i] = acc; acc += c; }
        }
        __syncthreads();
        if (threadIdx.x < DEG_BINS) g_degcursor[threadIdx.x] = sm[threadIdx.x];
    }
}

// Scan pass 3 (add block offsets) + degree-bucket permutation, fused.
__global__ void k_scan3_permute() {
    __shared__ int s_hist[DEG_BINS];
    __shared__ int s_base[DEG_BINS];
    if (threadIdx.x < DEG_BINS) s_hist[threadIdx.x] = 0;
    __syncthreads();
    int i = blockIdx.x * SCAN_BS + threadIdx.x;
    int bin = 0, rank = 0;
    if (i < NUM_NODES) {
        g_off[i] += g_bsums[blockIdx.x];
        int d = g_counts[i]; bin = (d > DEG_BINS - 1) ? DEG_BINS - 1 : d;
        rank = atomicAdd(&s_hist[bin], 1);
    }
    __syncthreads();
    if (threadIdx.x < DEG_BINS)
        s_base[threadIdx.x] = atomicAdd(&g_degcursor[threadIdx.x], s_hist[threadIdx.x]);
    __syncthreads();
    if (i < NUM_NODES) g_perm[s_base[bin] + rank] = i;
}

// Reorder bumps g_off directly: afterwards g_off[n] == segment END.
__global__ void k_reorder(const int* __restrict__ esrc,
                          const int* __restrict__ edst,
                          const float* __restrict__ eval) {
    int e = blockIdx.x * blockDim.x + threadIdx.x;
    if (e >= NUM_EDGES) return;
    int p = atomicAdd(&g_off[esrc[e]], 1);
    g_edges[p] = make_int2(edst[e], __float_as_int(eval[e]));
}

// ===========================================================================
// Segmented-sum layers: 8 lanes/node, fp32 accumulation, fp16 rows,
// 2-wide unroll (degree-uniform warps), no atomics.
// ===========================================================================
__device__ __forceinline__ void acc_h8(uint4 r, float v, float* a) {
    float2 f;
    f = __half22float2(*(const __half2*)&r.x); a[0] += f.x * v; a[1] += f.y * v;
    f = __half22float2(*(const __half2*)&r.y); a[2] += f.x * v; a[3] += f.y * v;
    f = __half22float2(*(const __half2*)&r.z); a[4] += f.x * v; a[5] += f.y * v;
    f = __half22float2(*(const __half2*)&r.w); a[6] += f.x * v; a[7] += f.y * v;
}

__device__ __forceinline__ uint4 pack_h8(const float* a) {
    uint4 o;
    *(__half2*)&o.x = __floats2half2_rn(a[0], a[1]);
    *(__half2*)&o.y = __floats2half2_rn(a[2], a[3]);
    *(__half2*)&o.z = __floats2half2_rn(a[4], a[5]);
    *(__half2*)&o.w = __floats2half2_rn(a[6], a[7]);
    return o;
}

__device__ __forceinline__ void seg_sum(const uint4* __restrict__ x,
                                        int beg, int end, int l, float* a) {
    int p = beg;
    for (; p + 2 <= end; p += 2) {
        int2 ea = __ldg(&g_edges[p]);
        int2 eb = __ldg(&g_edges[p + 1]);
        uint4 ra = __ldg(x + (long)ea.x * 8 + l);
        uint4 rb = __ldg(x + (long)eb.x * 8 + l);
        acc_h8(ra, __int_as_float(ea.y), a);
        acc_h8(rb, __int_as_float(eb.y), a);
    }
    if (p < end) {
        int2 e = __ldg(&g_edges[p]);
        uint4 r = __ldg(x + (long)e.x * 8 + l);
        acc_h8(r, __int_as_float(e.y), a);
    }
}

// Generic layer: fp16 x -> fp16 y   (layers 1 and 2)
__global__ void k_layer(const uint4* __restrict__ x,
                        uint4* __restrict__ y) {
    long t = (long)blockIdx.x * blockDim.x + threadIdx.x;
    long g = t >> 3;
    int  l = (int)(t & 7);
    if (g >= NUM_NODES) return;
    int n = g_perm[g];
    int end = g_off[n];
    int beg = end - g_counts[n];

    float a[8] = {0.f,0.f,0.f,0.f,0.f,0.f,0.f,0.f};
    seg_sum(x, beg, end, l, a);
    __stcs(y + (long)n * 8 + l, pack_h8(a));
}

// Layer 3 + fused epilogue: out = (x0_fp32 + B + C + x3)/4
__global__ void k_layer3_final(const uint4* __restrict__ x,      // C (x2)
                               const float4* __restrict__ user4,
                               const float4* __restrict__ item4,
                               const uint4* __restrict__ b,      // B (x1)
                               float4* __restrict__ out4) {
    long t = (long)blockIdx.x * blockDim.x + threadIdx.x;
    long g = t >> 3;
    int  l = (int)(t & 7);
    if (g >= NUM_NODES) return;
    int n = g_perm[g];
    int end = g_off[n];
    int beg = end - g_counts[n];

    float a[8] = {0.f,0.f,0.f,0.f,0.f,0.f,0.f,0.f};
    seg_sum(x, beg, end, l, a);

    const float4* x0 = (n < NUM_USERS) ? (user4 + (long)n * 16)
                                       : (item4 + (long)(n - NUM_USERS) * 16);
    float4 e0 = __ldg(x0 + 2 * l);
    float4 e1 = __ldg(x0 + 2 * l + 1);
    uint4 br = __ldg(b + (long)n * 8 + l);
    uint4 cr = __ldg(x + (long)n * 8 + l);
    float bb[8], cc[8];
    {
        float2 f;
        f = __half22float2(*(const __half2*)&br.x); bb[0]=f.x; bb[1]=f.y;
        f = __half22float2(*(const __half2*)&br.y); bb[2]=f.x; bb[3]=f.y;
        f = __half22float2(*(const __half2*)&br.z); bb[4]=f.x; bb[5]=f.y;
        f = __half22float2(*(const __half2*)&br.w); bb[6]=f.x; bb[7]=f.y;
        f = __half22float2(*(const __half2*)&cr.x); cc[0]=f.x; cc[1]=f.y;
        f = __half22float2(*(const __half2*)&cr.y); cc[2]=f.x; cc[3]=f.y;
        f = __half22float2(*(const __half2*)&cr.z); cc[4]=f.x; cc[5]=f.y;
        f = __half22float2(*(const __half2*)&cr.w); cc[6]=f.x; cc[7]=f.y;
    }
    float4 o0, o1;
    o0.x = (a[0] + e0.x + bb[0] + cc[0]) * 0.25f;
    o0.y = (a[1] + e0.y + bb[1] + cc[1]) * 0.25f;
    o0.z = (a[2] + e0.z + bb[2] + cc[2]) * 0.25f;
    o0.w = (a[3] + e0.w + bb[3] + cc[3]) * 0.25f;
    o1.x = (a[4] + e1.x + bb[4] + cc[4]) * 0.25f;
    o1.y = (a[5] + e1.y + bb[5] + cc[5]) * 0.25f;
    o1.z = (a[6] + e1.z + bb[6] + cc[6]) * 0.25f;
    o1.w = (a[7] + e1.w + bb[7] + cc[7]) * 0.25f;
    __stcs(out4 + (long)n * 16 + 2 * l,     o0);
    __stcs(out4 + (long)n * 16 + 2 * l + 1, o1);
}

// ===========================================================================
extern "C" void kernel_launch(void* const* d_in, const int* in_sizes, int n_in,
                              void* d_out, int out_size) {
    const float4* user4 = (const float4*)d_in[0];
    const float4* item4 = (const float4*)d_in[1];
    const float*  eval  = (const float*) d_in[2];
    const int*    esrc  = (const int*)   d_in[3];
    const int*    edst  = (const int*)   d_in[4];
    float4*       out4  = (float4*)d_out;

    void *pA, *pB, *pC, *pCnt, *pDh;
    cudaGetSymbolAddress(&pA,   g_bufA);
    cudaGetSymbolAddress(&pB,   g_bufB);
    cudaGetSymbolAddress(&pC,   g_bufC);
    cudaGetSymbolAddress(&pCnt, g_counts);
    cudaGetSymbolAddress(&pDh,  g_deghist);
    uint4* A = (uint4*)pA;
    uint4* B = (uint4*)pB;
    uint4* C = (uint4*)pC;

    const int TB = 256;
    const unsigned edge_blocks  = (NUM_EDGES + TB - 1) / TB;                       // 7813
    const unsigned group_blocks = (unsigned)(((long)NUM_NODES * 8 + TB - 1) / TB); // 9375

    // --- prep: zero counters (memset nodes), convert x0 + histogram fused ---
    cudaMemsetAsync(pCnt, 0, NUM_NODES * sizeof(int));
    cudaMemsetAsync(pDh,  0, DEG_BINS * sizeof(int));
    k_prep_hist    <<<group_blocks, TB>>>(user4, item4, A, esrc);
    k_scan1        <<<SCAN_NB, SCAN_BS>>>();
    k_scan2        <<<2, 1024>>>();
    k_scan3_permute<<<SCAN_NB, SCAN_BS>>>();
    k_reorder      <<<edge_blocks, TB>>>(esrc, edst, eval);

    // --- 3 propagation layers ---
    k_layer       <<<group_blocks, TB>>>(A, B);
    k_layer       <<<group_blocks, TB>>>(B, C);
    k_layer3_final<<<group_blocks, TB>>>(C, user4, item4, B, out4);
}

// round 9
// speedup vs baseline: 3.1509x; 1.1323x over previous
#include <cuda_runtime.h>
#include <cuda_fp16.h>
#include <cstdint>

#define NUM_USERS 100000
#define NUM_ITEMS 200000
#define NUM_NODES (NUM_USERS + NUM_ITEMS)
#define DIM 64
#define NUM_EDGES 2000000
#define NFLOAT ((long)NUM_NODES * DIM)

#define ASSIGN_BS 512
#define DEG_BINS 64

// ---- device-global scratch ----
__device__ __half g_bufA[NFLOAT];            // x0 (fp16 copy of inputs)
__device__ __half g_bufB[NFLOAT];            // x1 (fp16)
__device__ __half g_bufC[NFLOAT];            // x2 (fp16)
__device__ int2   g_edges[NUM_EDGES];        // segment-grouped {dst, val bits}
__device__ int    g_counts[NUM_NODES];
__device__ int    g_off[NUM_NODES];          // segment base; after reorder = segment END
__device__ int    g_perm[NUM_NODES];         // nodes grouped by degree
__device__ int    g_deghist[DEG_BINS];
__device__ int    g_degcursor[DEG_BINS];
__device__ int    g_total;                   // global edge-slot cursor

// ===========================================================================
// Prep: convert x0 -> fp16 A (8 lanes/node) AND build src-degree histogram.
// (g_counts / g_deghist / g_total zeroed beforehand via cudaMemsetAsync.)
// ===========================================================================
__global__ void k_prep_hist(const float4* __restrict__ user4,
                            const float4* __restrict__ item4,
                            uint4* __restrict__ a,
                            const int* __restrict__ esrc) {
    long t = (long)blockIdx.x * blockDim.x + threadIdx.x;
    if (t < NUM_EDGES) atomicAdd(&g_counts[esrc[t]], 1);

    long n = t >> 3;
    int  l = (int)(t & 7);
    if (n >= NUM_NODES) return;
    const float4* x0 = (n < NUM_USERS) ? (user4 + n * 16)
                                       : (item4 + (n - NUM_USERS) * 16);
    float4 m0 = __ldg(x0 + 2 * l);
    float4 m1 = __ldg(x0 + 2 * l + 1);
    uint4 o;
    *(__half2*)&o.x = __floats2half2_rn(m0.x, m0.y);
    *(__half2*)&o.y = __floats2half2_rn(m0.z, m0.w);
    *(__half2*)&o.z = __floats2half2_rn(m1.x, m1.y);
    *(__half2*)&o.w = __floats2half2_rn(m1.z, m1.w);
    __stcs(a + n * 8 + l, o);
}

// ===========================================================================
// Single-pass segment-base assignment: block-local scan of counts + ONE
// atomicAdd on a global cursor per block (segment order is arbitrary —
// harmless). Also builds the degree histogram.
// ===========================================================================
__global__ void k_assign() {
    __shared__ int sm[ASSIGN_BS];
    __shared__ int sh[DEG_BINS];
    __shared__ int s_base;
    if (threadIdx.x < DEG_BINS) sh[threadIdx.x] = 0;
    int i = blockIdx.x * ASSIGN_BS + threadIdx.x;
    int v = (i < NUM_NODES) ? g_counts[i] : 0;
    sm[threadIdx.x] = v; __syncthreads();
    if (i < NUM_NODES) {
        int bin = (v > DEG_BINS - 1) ? DEG_BINS - 1 : v;
        atomicAdd(&sh[bin], 1);
    }
    #pragma unroll
    for (int ofs = 1; ofs < ASSIGN_BS; ofs <<= 1) {
        int t = (threadIdx.x >= ofs) ? sm[threadIdx.x - ofs] : 0;
        __syncthreads();
        sm[threadIdx.x] += t;
        __syncthreads();
    }
    if (threadIdx.x == ASSIGN_BS - 1)
        s_base = atomicAdd(&g_total, sm[ASSIGN_BS - 1]);
    __syncthreads();
    if (i < NUM_NODES) g_off[i] = s_base + sm[threadIdx.x] - v;  // exclusive base
    if (threadIdx.x < DEG_BINS && sh[threadIdx.x])
        atomicAdd(&g_deghist[threadIdx.x], sh[threadIdx.x]);
}

// Tiny serial scan of 64 degree bins -> bucket cursors.
__global__ void k_degscan() {
    __shared__ int sm[DEG_BINS];
    if (threadIdx.x < DEG_BINS) sm[threadIdx.x] = g_deghist[threadIdx.x];
    __syncthreads();
    if (threadIdx.x == 0) {
        int acc = 0;
        for (int i = 0; i < DEG_BINS; ++i) { int c = sm[i]; sm[i] = acc; acc += c; }
    }
    __syncthreads();
    if (threadIdx.x < DEG_BINS) g_degcursor[threadIdx.x] = sm[threadIdx.x];
}

// ===========================================================================
// Fused: (a) degree-bucket permutation (node range), (b) edge reorder into
// segments (edge range). Independent jobs; reorder bumps g_off so afterwards
// g_off[n] == segment END.
// ===========================================================================
__global__ void k_reorder_permute(const int* __restrict__ esrc,
                                  const int* __restrict__ edst,
                                  const float* __restrict__ eval) {
    __shared__ int s_hist[DEG_BINS];
    __shared__ int s_base[DEG_BINS];
    if (threadIdx.x < DEG_BINS) s_hist[threadIdx.x] = 0;
    __syncthreads();
    long t = (long)blockIdx.x * blockDim.x + threadIdx.x;
    int bin = 0, rank = 0;
    bool node_ok = (t < NUM_NODES);
    if (node_ok) {
        int d = g_counts[t]; bin = (d > DEG_BINS - 1) ? DEG_BINS - 1 : d;
        rank = atomicAdd(&s_hist[bin], 1);
    }
    __syncthreads();
    if (threadIdx.x < DEG_BINS && s_hist[threadIdx.x])
        s_base[threadIdx.x] = atomicAdd(&g_degcursor[threadIdx.x], s_hist[threadIdx.x]);
    __syncthreads();
    if (node_ok) g_perm[s_base[bin] + rank] = (int)t;

    if (t < NUM_EDGES) {
        int p = atomicAdd(&g_off[esrc[t]], 1);
        g_edges[p] = make_int2(edst[t], __float_as_int(eval[t]));
    }
}

// ===========================================================================
// Segmented-sum layers: 8 lanes/node, fp32 accumulation, fp16 rows,
// 4-wide unroll for MLP (degree-uniform warps), no atomics.
// ===========================================================================
__device__ __forceinline__ void acc_h8(uint4 r, float v, float* a) {
    float2 f;
    f = __half22float2(*(const __half2*)&r.x); a[0] += f.x * v; a[1] += f.y * v;
    f = __half22float2(*(const __half2*)&r.y); a[2] += f.x * v; a[3] += f.y * v;
    f = __half22float2(*(const __half2*)&r.z); a[4] += f.x * v; a[5] += f.y * v;
    f = __half22float2(*(const __half2*)&r.w); a[6] += f.x * v; a[7] += f.y * v;
}

__device__ __forceinline__ uint4 pack_h8(const float* a) {
    uint4 o;
    *(__half2*)&o.x = __floats2half2_rn(a[0], a[1]);
    *(__half2*)&o.y = __floats2half2_rn(a[2], a[3]);
    *(__half2*)&o.z = __floats2half2_rn(a[4], a[5]);
    *(__half2*)&o.w = __floats2half2_rn(a[6], a[7]);
    return o;
}

__device__ __forceinline__ void seg_sum(const uint4* __restrict__ x,
                                        int beg, int end, int l, float* a) {
    int p = beg;
    for (; p + 4 <= end; p += 4) {
        int2 e0 = __ldg(&g_edges[p]);
        int2 e1 = __ldg(&g_edges[p + 1]);
        int2 e2 = __ldg(&g_edges[p + 2]);
        int2 e3 = __ldg(&g_edges[p + 3]);
        uint4 r0 = __ldg(x + (long)e0.x * 8 + l);
        uint4 r1 = __ldg(x + (long)e1.x * 8 + l);
        uint4 r2 = __ldg(x + (long)e2.x * 8 + l);
        uint4 r3 = __ldg(x + (long)e3.x * 8 + l);
        acc_h8(r0, __int_as_float(e0.y), a);
        acc_h8(r1, __int_as_float(e1.y), a);
        acc_h8(r2, __int_as_float(e2.y), a);
        acc_h8(r3, __int_as_float(e3.y), a);
    }
    if (p + 2 <= end) {
        int2 e0 = __ldg(&g_edges[p]);
        int2 e1 = __ldg(&g_edges[p + 1]);
        uint4 r0 = __ldg(x + (long)e0.x * 8 + l);
        uint4 r1 = __ldg(x + (long)e1.x * 8 + l);
        acc_h8(r0, __int_as_float(e0.y), a);
        acc_h8(r1, __int_as_float(e1.y), a);
        p += 2;
    }
    if (p < end) {
        int2 e = __ldg(&g_edges[p]);
        uint4 r = __ldg(x + (long)e.x * 8 + l);
        acc_h8(r, __int_as_float(e.y), a);
    }
}

// Generic layer: fp16 x -> fp16 y   (layers 1 and 2)
__global__ void k_layer(const uint4* __restrict__ x,
                        uint4* __restrict__ y) {
    long t = (long)blockIdx.x * blockDim.x + threadIdx.x;
    long g = t >> 3;
    int  l = (int)(t & 7);
    if (g >= NUM_NODES) return;
    int n = g_perm[g];
    int end = g_off[n];
    int beg = end - g_counts[n];

    float a[8] = {0.f,0.f,0.f,0.f,0.f,0.f,0.f,0.f};
    seg_sum(x, beg, end, l, a);
    __stcs(y + (long)n * 8 + l, pack_h8(a));
}

// Layer 3 + fused epilogue: out = (x0_fp32 + B + C + x3)/4
__global__ void k_layer3_final(const uint4* __restrict__ x,      // C (x2)
                               const float4* __restrict__ user4,
                               const float4* __restrict__ item4,
                               const uint4* __restrict__ b,      // B (x1)
                               float4* __restrict__ out4) {
    long t = (long)blockIdx.x * blockDim.x + threadIdx.x;
    long g = t >> 3;
    int  l = (int)(t & 7);
    if (g >= NUM_NODES) return;
    int n = g_perm[g];
    int end = g_off[n];
    int beg = end - g_counts[n];

    float a[8] = {0.f,0.f,0.f,0.f,0.f,0.f,0.f,0.f};
    seg_sum(x, beg, end, l, a);

    const float4* x0 = (n < NUM_USERS) ? (user4 + (long)n * 16)
                                       : (item4 + (long)(n - NUM_USERS) * 16);
    float4 e0 = __ldg(x0 + 2 * l);
    float4 e1 = __ldg(x0 + 2 * l + 1);
    uint4 br = __ldg(b + (long)n * 8 + l);
    uint4 cr = __ldg(x + (long)n * 8 + l);
    float bb[8], cc[8];
    {
        float2 f;
        f = __half22float2(*(const __half2*)&br.x); bb[0]=f.x; bb[1]=f.y;
        f = __half22float2(*(const __half2*)&br.y); bb[2]=f.x; bb[3]=f.y;
        f = __half22float2(*(const __half2*)&br.z); bb[4]=f.x; bb[5]=f.y;
        f = __half22float2(*(const __half2*)&br.w); bb[6]=f.x; bb[7]=f.y;
        f = __half22float2(*(const __half2*)&cr.x); cc[0]=f.x; cc[1]=f.y;
        f = __half22float2(*(const __half2*)&cr.y); cc[2]=f.x; cc[3]=f.y;
        f = __half22float2(*(const __half2*)&cr.z); cc[4]=f.x; cc[5]=f.y;
        f = __half22float2(*(const __half2*)&cr.w); cc[6]=f.x; cc[7]=f.y;
    }
    float4 o0, o1;
    o0.x = (a[0] + e0.x + bb[0] + cc[0]) * 0.25f;
    o0.y = (a[1] + e0.y + bb[1] + cc[1]) * 0.25f;
    o0.z = (a[2] + e0.z + bb[2] + cc[2]) * 0.25f;
    o0.w = (a[3] + e0.w + bb[3] + cc[3]) * 0.25f;
    o1.x = (a[4] + e1.x + bb[4] + cc[4]) * 0.25f;
    o1.y = (a[5] + e1.y + bb[5] + cc[5]) * 0.25f;
    o1.z = (a[6] + e1.z + bb[6] + cc[6]) * 0.25f;
    o1.w = (a[7] + e1.w + bb[7] + cc[7]) * 0.25f;
    __stcs(out4 + (long)n * 16 + 2 * l,     o0);
    __stcs(out4 + (long)n * 16 + 2 * l + 1, o1);
}

// ===========================================================================
extern "C" void kernel_launch(void* const* d_in, const int* in_sizes, int n_in,
                              void* d_out, int out_size) {
    const float4* user4 = (const float4*)d_in[0];
    const float4* item4 = (const float4*)d_in[1];
    const float*  eval  = (const float*) d_in[2];
    const int*    esrc  = (const int*)   d_in[3];
    const int*    edst  = (const int*)   d_in[4];
    float4*       out4  = (float4*)d_out;

    void *pA, *pB, *pC, *pCnt, *pDh, *pTot;
    cudaGetSymbolAddress(&pA,   g_bufA);
    cudaGetSymbolAddress(&pB,   g_bufB);
    cudaGetSymbolAddress(&pC,   g_bufC);
    cudaGetSymbolAddress(&pCnt, g_counts);
    cudaGetSymbolAddress(&pDh,  g_deghist);
    cudaGetSymbolAddress(&pTot, g_total);
    uint4* A = (uint4*)pA;
    uint4* B = (uint4*)pB;
    uint4* C = (uint4*)pC;

    const int TB = 256;
    const unsigned group_blocks = (unsigned)(((long)NUM_NODES * 8 + TB - 1) / TB); // 9375
    const unsigned fuse_blocks  = (NUM_EDGES + TB - 1) / TB;                       // 7813
    const unsigned assign_blocks = (NUM_NODES + ASSIGN_BS - 1) / ASSIGN_BS;        // 586

    // --- prep ---
    cudaMemsetAsync(pCnt, 0, NUM_NODES * sizeof(int));
    cudaMemsetAsync(pDh,  0, DEG_BINS * sizeof(int));
    cudaMemsetAsync(pTot, 0, sizeof(int));
    k_prep_hist      <<<group_blocks, TB>>>(user4, item4, A, esrc);
    k_assign         <<<assign_blocks, ASSIGN_BS>>>();
    k_degscan        <<<1, DEG_BINS>>>();
    k_reorder_permute<<<fuse_blocks, TB>>>(esrc, edst, eval);

    // --- 3 propagation layers ---
    k_layer       <<<group_blocks, TB>>>(A, B);
    k_layer       <<<group_blocks, TB>>>(B, C);
    k_layer3_final<<<group_blocks, TB>>>(C, user4, item4, B, out4);
}